// round 14
// baseline (speedup 1.0000x reference)
#include <cuda_runtime.h>
#include <cuda_bf16.h>
#include <math.h>
#include <stdint.h>

#define B_SZ 8
#define LSEQ 200
#define DM   256
#define DI   512
#define DS   64
#define DTR  16
#define NB   4
#define MROWS (B_SZ*LSEQ)      /* 1600 */
#define XP_N  (DTR + 2*DS)     /* 144 real columns  */
#define XP_P  192              /* padded stride     */
#define OSPLIT 4               /* splitK for the out GEMM */
#define XSPLIT 4               /* splitK for the xp GEMM  */
#define NDP   (DI/2)           /* 256 d-pairs */
#define SB    8                /* scan reduction batch */

/* ---------------- scratch (device globals; no runtime allocation) -------- */
__device__ float g_xz [MROWS * 2 * DI];
__device__ float g_xm [MROWS * DI];
__device__ float g_xps[XSPLIT * MROWS * XP_P];   /* xp splitK slices */
__device__ float g_xp [MROWS * XP_P];            /* final xp (+phase) */
__device__ float g_o  [OSPLIT * MROWS * DM];
/* packed scan stream: [(b*NDP+dp)*LSEQ + t] * 8 floats = dt0,dt1,u0,u1,z0,z1 */
__device__ float g_pack[B_SZ * NDP * LSEQ * 8];

/* fragment-ordered bf16 hi/lo operand arrays */
__device__ uint32_t g_xperm [(MROWS/16) * (DM/16) * 32 * 8];   /* A of xz  */
__device__ uint32_t g_winp  [(2*DI/8) * (DM/16) * 32 * 4];     /* B of xz  */
__device__ uint32_t g_xmperm[(MROWS/16) * (DI/16) * 32 * 8];   /* A of xp  */
__device__ uint32_t g_wxp   [(XP_P/8) * (DI/16) * 32 * 4];     /* B of xp  */
__device__ uint32_t g_yperm [(MROWS/16) * (DI/16) * 32 * 8];   /* A of out */
__device__ uint32_t g_woutp [(DM/8) * (DI/16) * 32 * 4];       /* B of out */

__device__ __forceinline__ float softplusf(float x) {
    return x > 20.f ? x : __logf(1.f + __expf(x));
}
__device__ __forceinline__ float siluf(float x) {
    return x / (1.f + __expf(-x));
}
__device__ __forceinline__ float warp_sum(float v) {
#pragma unroll
    for (int o = 16; o; o >>= 1) v += __shfl_xor_sync(0xffffffffu, v, o);
    return v;
}

/* pack (a,b) -> bf16x2 hi + residual bf16x2 lo */
__device__ __forceinline__ void bf16split2(float a, float b,
                                           uint32_t& hi, uint32_t& lo) {
    __nv_bfloat16 ha = __float2bfloat16(a);
    __nv_bfloat16 hb = __float2bfloat16(b);
    float ra = a - __bfloat162float(ha);
    float rb = b - __bfloat162float(hb);
    __nv_bfloat16 la = __float2bfloat16(ra);
    __nv_bfloat16 lb = __float2bfloat16(rb);
    hi = ((uint32_t)*(uint16_t*)&hb << 16) | *(uint16_t*)&ha;
    lo = ((uint32_t)*(uint16_t*)&lb << 16) | *(uint16_t*)&la;
}

/* ---------------- fused operand permute+split ----------------------------- */
__device__ __forceinline__ void aperm_body(const float* __restrict__ A,
                                           uint32_t* __restrict__ Ap,
                                           int j, int M, int K) {
    int KH = K >> 1;
    int m = j / KH, k = (j - m * KH) * 2;
    float2 v = *(const float2*)(A + (size_t)m * K + k);
    uint32_t hi, lo;
    bf16split2(v.x, v.y, hi, lo);
    int KT = K >> 4;
    int mt = m >> 4, kt = k >> 4;
    int lane = (m & 7) * 4 + ((k & 7) >> 1);
    int reg  = ((m >> 3) & 1) + (((k >> 3) & 1) << 1);
    size_t idx = ((((size_t)mt * KT + kt) * 32 + lane) << 3) + reg;
    Ap[idx]     = hi;
    Ap[idx + 4] = lo;
}
__device__ __forceinline__ void bperm_body(const float* __restrict__ B,
                                           uint32_t* __restrict__ Bp,
                                           int j, int K, int ldb, int Nreal) {
    int KH = K >> 1;
    int n = j / KH, k = (j - n * KH) * 2;
    float a = (n < Nreal) ? B[(size_t)k * ldb + n] : 0.f;
    float b = (n < Nreal) ? B[(size_t)(k + 1) * ldb + n] : 0.f;
    uint32_t hi, lo;
    bf16split2(a, b, hi, lo);
    int KT = K >> 4;
    int n8 = n >> 3, kt = k >> 4;
    int lane = (n & 7) * 4 + ((k & 7) >> 1);
    int reg  = (k >> 3) & 1;
    size_t idx = ((((size_t)n8 * KT + kt) * 32 + lane) << 2) + reg;
    Bp[idx]     = hi;
    Bp[idx + 2] = lo;
}

#define PERM_NA  ((MROWS * DM / 2) / 256)        /* 800 */
#define PERM_NB1 ((2 * DI * DM / 2) / 256)       /* 512 */
#define PERM_NB2 ((DM * DI / 2) / 256)           /* 256 */
#define PERM_NB3 ((XP_P * DI / 2) / 256)         /* 192 */

__global__ __launch_bounds__(256) void perm_all_kernel(
    const float* __restrict__ x, const float* __restrict__ W_in,
    const float* __restrict__ W_out, const float* __restrict__ W_x) {
    int bid = blockIdx.x, tid = threadIdx.x;
    if (bid < PERM_NA) {
        aperm_body(x, g_xperm, bid * 256 + tid, MROWS, DM);
    } else if (bid < PERM_NA + PERM_NB1) {
        bperm_body(W_in, g_winp, (bid - PERM_NA) * 256 + tid,
                   DM, 2 * DI, 2 * DI);
    } else if (bid < PERM_NA + PERM_NB1 + PERM_NB2) {
        bperm_body(W_out, g_woutp, (bid - PERM_NA - PERM_NB1) * 256 + tid,
                   DI, DM, DM);
    } else {
        bperm_body(W_x, g_wxp, (bid - PERM_NA - PERM_NB1 - PERM_NB2) * 256 + tid,
                   DI, XP_N, XP_N);
    }
}

/* ------ bf16-split tensor GEMM, warp tile 32x16, register prefetch ------- */
__device__ __forceinline__ void mma_bf16(float* c, const uint32_t* a,
                                         const uint32_t* b) {
    asm volatile(
        "mma.sync.aligned.m16n8k16.row.col.f32.bf16.bf16.f32 "
        "{%0,%1,%2,%3},{%4,%5,%6,%7},{%8,%9},{%0,%1,%2,%3};"
        : "+f"(c[0]), "+f"(c[1]), "+f"(c[2]), "+f"(c[3])
        : "r"(a[0]), "r"(a[1]), "r"(a[2]), "r"(a[3]), "r"(b[0]), "r"(b[1]));
}

template<int NKT>
__global__ __launch_bounds__(256) void gemm_bf16_kernel(
    const uint32_t* __restrict__ Ap, const uint32_t* __restrict__ Bp,
    float* __restrict__ C, int ldc, int KT, int sliceElems)
{
    const int lane   = threadIdx.x & 31;
    const int warpid = threadIdx.x >> 5;
    const int wm = warpid & 1, wn = warpid >> 1;
    const int ktBegin = blockIdx.z * NKT;
    C += (size_t)blockIdx.z * sliceElems;
    const int mt0 = blockIdx.y * 4 + wm * 2;
    const int n80 = blockIdx.x * 8 + wn * 2;

    float acc[2][2][4] = {};
    uint4 ah[2][2], al[2][2], bfr[2][2];

    auto loadk = [&](int kt, int s) {
#pragma unroll
        for (int mt = 0; mt < 2; mt++) {
            const uint32_t* p =
                Ap + ((((size_t)(mt0 + mt) * KT + kt) * 32 + lane) << 3);
            ah[s][mt] = *(const uint4*)p;
            al[s][mt] = *(const uint4*)(p + 4);
        }
#pragma unroll
        for (int nt = 0; nt < 2; nt++)
            bfr[s][nt] = *(const uint4*)(
                Bp + ((((size_t)(n80 + nt) * KT + kt) * 32 + lane) << 2));
    };

    loadk(ktBegin, 0);
#pragma unroll
    for (int kk = 0; kk < NKT; kk++) {
        const int cur = kk & 1;
        if (kk + 1 < NKT) loadk(ktBegin + kk + 1, cur ^ 1);
#pragma unroll
        for (int mt = 0; mt < 2; mt++)
#pragma unroll
            for (int nt = 0; nt < 2; nt++) {
                uint32_t bh[2] = {bfr[cur][nt].x, bfr[cur][nt].y};
                uint32_t bl[2] = {bfr[cur][nt].z, bfr[cur][nt].w};
                mma_bf16(acc[mt][nt], (const uint32_t*)&ah[cur][mt], bh);
                mma_bf16(acc[mt][nt], (const uint32_t*)&ah[cur][mt], bl);
                mma_bf16(acc[mt][nt], (const uint32_t*)&al[cur][mt], bh);
            }
    }

    const int g = lane >> 2, tig = lane & 3;
#pragma unroll
    for (int mt = 0; mt < 2; mt++) {
        int r = (mt0 + mt) * 16 + g;
#pragma unroll
        for (int nt = 0; nt < 2; nt++) {
            int c = (n80 + nt) * 8 + tig * 2;
            *(float2*)&C[(size_t)r * ldc + c] =
                make_float2(acc[mt][nt][0], acc[mt][nt][1]);
            *(float2*)&C[(size_t)(r + 8) * ldc + c] =
                make_float2(acc[mt][nt][2], acc[mt][nt][3]);
        }
    }
}

/* -- depthwise causal conv (k=4) + SiLU, 4 d/thread; emits xm + fragments - */
__global__ __launch_bounds__(256) void conv_silu_kernel(
    const float* __restrict__ conv_w, const float* __restrict__ conv_b) {
    int idx = blockIdx.x * blockDim.x + threadIdx.x;
    if (idx >= MROWS * (DI / 4)) return;
    int d0  = (idx % (DI / 4)) * 4;
    int row = idx / (DI / 4);
    int l = row % LSEQ;
    const float* xzbase = g_xz + (size_t)row * (2 * DI) + d0;

    float4 acc = *(const float4*)(conv_b + d0);
    float4 w0 = *(const float4*)(conv_w + (d0 + 0) * 4);
    float4 w1 = *(const float4*)(conv_w + (d0 + 1) * 4);
    float4 w2 = *(const float4*)(conv_w + (d0 + 2) * 4);
    float4 w3 = *(const float4*)(conv_w + (d0 + 3) * 4);
    const float* wk[4] = {(const float*)&w0, (const float*)&w1,
                          (const float*)&w2, (const float*)&w3};
#pragma unroll
    for (int k = 0; k < 4; k++) {
        int li = l - 3 + k;
        if (li >= 0) {
            float4 xv = *(const float4*)(xzbase + (size_t)(li - l) * (2 * DI));
            acc.x += wk[0][k] * xv.x;
            acc.y += wk[1][k] * xv.y;
            acc.z += wk[2][k] * xv.z;
            acc.w += wk[3][k] * xv.w;
        }
    }
    float4 o;
    o.x = siluf(acc.x); o.y = siluf(acc.y);
    o.z = siluf(acc.z); o.w = siluf(acc.w);
    *(float4*)(g_xm + (size_t)row * DI + d0) = o;

    uint32_t hi0, lo0, hi1, lo1;
    bf16split2(o.x, o.y, hi0, lo0);
    bf16split2(o.z, o.w, hi1, lo1);
    int mt = row >> 4, kt = d0 >> 4;
    int lane0 = (row & 7) * 4 + ((d0 & 7) >> 1);
    int reg   = ((row >> 3) & 1) + (((d0 >> 3) & 1) << 1);
    size_t base = ((((size_t)mt * (DI / 16) + kt) * 32 + lane0) << 3) + reg;
    g_xmperm[base]      = hi0;
    g_xmperm[base + 4]  = lo0;
    g_xmperm[base + 8]  = hi1;
    g_xmperm[base + 12] = lo1;
}

/* --- xp slice-sum + phase-add + dt + scan-stream pack --------------------- */
__global__ __launch_bounds__(256) void dt_phase_kernel(
    const float* __restrict__ W_dt, const float* __restrict__ b_dt,
    const float* __restrict__ delta_mag,
    const float* __restrict__ cosp, const float* __restrict__ sinp,
    const float* __restrict__ Wph) {
    int row = blockIdx.x * 4 + (threadIdx.x >> 6);
    int t64 = threadIdx.x & 63;
    int b = row / LSEQ, l = row % LSEQ;

    float ph[2 * NB];
#pragma unroll
    for (int jb = 0; jb < NB; jb++) {
        ph[jb]      = cosp[(b * NB + jb) * LSEQ + l];
        ph[NB + jb] = sinp[(b * NB + jb) * LSEQ + l];
    }

#pragma unroll
    for (int q = 0; q < 3; q++) {
        int c = t64 + q * 64;
        if (c < XP_N) {
            size_t off = (size_t)row * XP_P + c;
            float s = 0.f;
#pragma unroll
            for (int sl = 0; sl < XSPLIT; sl++)
                s += g_xps[(size_t)sl * MROWS * XP_P + off];
            if (c >= DTR + DS) {
                int n = c - (DTR + DS);
#pragma unroll
                for (int j = 0; j < 2 * NB; j++) s += ph[j] * Wph[j * DS + n];
            }
            g_xp[off] = s;
        }
    }
    __syncthreads();

    int d0 = t64 * 8;
    float dl[DTR];
    {
        const float4* p = (const float4*)(g_xp + (size_t)row * XP_P);
#pragma unroll
        for (int q = 0; q < DTR / 4; q++) {
            float4 v = p[q];
            dl[q * 4 + 0] = v.x; dl[q * 4 + 1] = v.y;
            dl[q * 4 + 2] = v.z; dl[q * 4 + 3] = v.w;
        }
    }
    float4 acc0 = *(const float4*)(b_dt + d0);
    float4 acc1 = *(const float4*)(b_dt + d0 + 4);
#pragma unroll
    for (int r = 0; r < DTR; r++) {
        float4 w0 = *(const float4*)(W_dt + r * DI + d0);
        float4 w1 = *(const float4*)(W_dt + r * DI + d0 + 4);
        acc0.x += dl[r] * w0.x;  acc0.y += dl[r] * w0.y;
        acc0.z += dl[r] * w0.z;  acc0.w += dl[r] * w0.w;
        acc1.x += dl[r] * w1.x;  acc1.y += dl[r] * w1.y;
        acc1.z += dl[r] * w1.z;  acc1.w += dl[r] * w1.w;
    }
    float dmm = 0.25f * (delta_mag[(b * NB + 0) * LSEQ + l] +
                         delta_mag[(b * NB + 1) * LSEQ + l] +
                         delta_mag[(b * NB + 2) * LSEQ + l] +
                         delta_mag[(b * NB + 3) * LSEQ + l]);
    float scale = 1.f + softplusf(dmm);
    float dt8[8];
    dt8[0] = softplusf(acc0.x) * scale;  dt8[1] = softplusf(acc0.y) * scale;
    dt8[2] = softplusf(acc0.z) * scale;  dt8[3] = softplusf(acc0.w) * scale;
    dt8[4] = softplusf(acc1.x) * scale;  dt8[5] = softplusf(acc1.y) * scale;
    dt8[6] = softplusf(acc1.z) * scale;  dt8[7] = softplusf(acc1.w) * scale;

    float4 u0 = *(const float4*)(g_xm + (size_t)row * DI + d0);
    float4 u1 = *(const float4*)(g_xm + (size_t)row * DI + d0 + 4);
    float4 z0 = *(const float4*)(g_xz + (size_t)row * (2 * DI) + DI + d0);
    float4 z1 = *(const float4*)(g_xz + (size_t)row * (2 * DI) + DI + d0 + 4);
    float uu[8] = {u0.x, u0.y, u0.z, u0.w, u1.x, u1.y, u1.z, u1.w};
    float zz[8] = {z0.x, z0.y, z0.z, z0.w, z1.x, z1.y, z1.z, z1.w};
    int dpBase = (d0 >> 1);
#pragma unroll
    for (int p = 0; p < 4; p++) {
        int dp = dpBase + p;
        float* pk = g_pack + (((size_t)(b * NDP + dp)) * LSEQ + l) * 8;
        *(float4*)pk = make_float4(dt8[2*p], dt8[2*p+1], uu[2*p], uu[2*p+1]);
        *(float2*)(pk + 4) = make_float2(zz[2*p], zz[2*p+1]);
    }
}

/* -- selective scan: warp per (b,d-pair); 8-step batched reduction -------- */
__global__ __launch_bounds__(128) void scan_kernel(
    const float* __restrict__ A_log, const float* __restrict__ D_skip) {
    int warp = (blockIdx.x * blockDim.x + threadIdx.x) >> 5;
    int lane = threadIdx.x & 31;
    int b  = warp >> 8;
    int dp = warp & 255;
    int d0 = dp * 2;

    float2 a0 = *(const float2*)(A_log + (size_t)d0 * DS + 2 * lane);
    float2 a1 = *(const float2*)(A_log + (size_t)(d0 + 1) * DS + 2 * lane);
    float A00 = -__expf(a0.x), A01 = -__expf(a0.y);
    float A10 = -__expf(a1.x), A11 = -__expf(a1.y);
    float2 Dd = *(const float2*)(D_skip + d0);

    float h00 = 0.f, h01 = 0.f, h10 = 0.f, h11 = 0.f;

    const float* xpB = g_xp + (size_t)(b * LSEQ) * XP_P + DTR + 2 * lane;
    const float* pk  = g_pack + ((size_t)(b * NDP + dp)) * LSEQ * 8;

    const int half = lane >> 4;
    const bool isL0  = (lane == 0);
    const bool isL16 = (lane == 16);
    const int rowBase = b * LSEQ;
    const int ktd   = d0 >> 4;
    const int lane_c = (d0 & 7) >> 1;
    const int reg_c  = ((d0 >> 3) & 1) << 1;

    float2 Bs[SB], Cs[SB], zs[SB];
    float4 ps[SB];
#pragma unroll
    for (int s = 0; s < SB; s++) {
        const float* p = xpB + (size_t)s * XP_P;
        Bs[s] = *(const float2*)(p);
        Cs[s] = *(const float2*)(p + DS);
        ps[s] = *(const float4*)(pk + s * 8);
        zs[s] = *(const float2*)(pk + s * 8 + 4);
    }

#pragma unroll 1
    for (int t = 0; t < LSEQ; t += SB) {
        float p0s[SB], p1s[SB];
        float2 zsv[SB];
        /* phase 1: recurrence for SB steps + prefetch; fold u*D on lanes 0/16 */
#pragma unroll
        for (int s = 0; s < SB; s++) {
            float4 pv = ps[s];
            float2 z = zs[s], Bv = Bs[s], Cv = Cs[s];
            int tn = t + SB + s;
            if (tn < LSEQ) {
                const float* p = xpB + (size_t)tn * XP_P;
                Bs[s] = *(const float2*)(p);
                Cs[s] = *(const float2*)(p + DS);
                ps[s] = *(const float4*)(pk + (size_t)tn * 8);
                zs[s] = *(const float2*)(pk + (size_t)tn * 8 + 4);
            }
            float e00 = __expf(pv.x * A00), e01 = __expf(pv.x * A01);
            float e10 = __expf(pv.y * A10), e11 = __expf(pv.y * A11);
            float du0 = pv.x * pv.z, du1 = pv.y * pv.w;
            h00 = fmaf(e00, h00, du0 * Bv.x);
            h01 = fmaf(e01, h01, du0 * Bv.y);
            h10 = fmaf(e10, h10, du1 * Bv.x);
            h11 = fmaf(e11, h11, du1 * Bv.y);
            p0s[s] = fmaf(h01, Cv.y, h00 * Cv.x);
            p1s[s] = fmaf(h11, Cv.y, h10 * Cv.x);
            if (isL0)  p0s[s] += pv.z * Dd.x;   /* fold u0*D0 */
            if (isL16) p1s[s] += pv.w * Dd.y;   /* fold u1*D1 */
            zsv[s] = z;
        }
        /* phase 2: SB independent butterflies, pipelined rounds */
        float v[SB];
#pragma unroll
        for (int s = 0; s < SB; s++) {
            float q0 = __shfl_xor_sync(0xffffffffu, p0s[s], 16);
            float q1 = __shfl_xor_sync(0xffffffffu, p1s[s], 16);
            v[s] = half ? (p1s[s] + q1) : (p0s[s] + q0);
        }
#pragma unroll
        for (int o = 8; o; o >>= 1) {
#pragma unroll
            for (int s = 0; s < SB; s++)
                v[s] += __shfl_xor_sync(0xffffffffu, v[s], o);
        }
        float v1[SB];
#pragma unroll
        for (int s = 0; s < SB; s++)
            v1[s] = __shfl_sync(0xffffffffu, v[s], 16);
        /* phase 3: stores (lane 0, off critical path) */
        if (isL0) {
#pragma unroll
            for (int s = 0; s < SB; s++) {
                float y0 = v[s]  * siluf(zsv[s].x);
                float y1 = v1[s] * siluf(zsv[s].y);
                int m = rowBase + t + s;
                int lanep = (m & 7) * 4 + lane_c;
                int reg   = ((m >> 3) & 1) + reg_c;
                size_t idx = ((((size_t)(m >> 4) * (DI / 16) + ktd) * 32
                               + lanep) << 3) + reg;
                uint32_t hi, lo;
                bf16split2(y0, y1, hi, lo);
                g_yperm[idx]     = hi;
                g_yperm[idx + 4] = lo;
            }
        }
    }
}

/* --------- residual add + sum of splitK slices + LayerNorm --------------- */
__global__ void ln_kernel(const float* __restrict__ x,
                          const float* __restrict__ gamma,
                          const float* __restrict__ beta,
                          float* __restrict__ out) {
    int row = blockIdx.x;
    int c = threadIdx.x;
    float v = x[(size_t)row * DM + c];
#pragma unroll
    for (int s = 0; s < OSPLIT; s++)
        v += g_o[(size_t)s * MROWS * DM + (size_t)row * DM + c];

    float sum  = warp_sum(v);
    float sum2 = warp_sum(v * v);
    __shared__ float ws[8], ws2[8];
    int w = c >> 5, lane = c & 31;
    if (lane == 0) { ws[w] = sum; ws2[w] = sum2; }
    __syncthreads();
    float tot = 0.f, tot2 = 0.f;
#pragma unroll
    for (int i = 0; i < 8; i++) { tot += ws[i]; tot2 += ws2[i]; }
    float mu  = tot * (1.f / DM);
    float var = tot2 * (1.f / DM) - mu * mu;
    out[(size_t)row * DM + c] = (v - mu) * rsqrtf(var + 1e-12f) * gamma[c] + beta[c];
}

/* ---------------- launch --------------------------------------------------*/
extern "C" void kernel_launch(void* const* d_in, const int* in_sizes, int n_in,
                              void* d_out, int out_size) {
    const float* x         = (const float*)d_in[0];
    const float* cos_phi   = (const float*)d_in[1];
    const float* sin_phi   = (const float*)d_in[2];
    const float* delta_mag = (const float*)d_in[3];
    const float* W_in      = (const float*)d_in[4];
    const float* conv_w    = (const float*)d_in[5];
    const float* conv_b    = (const float*)d_in[6];
    const float* W_x       = (const float*)d_in[7];
    const float* W_dt      = (const float*)d_in[8];
    const float* b_dt      = (const float*)d_in[9];
    const float* A_log     = (const float*)d_in[10];
    const float* D_skip    = (const float*)d_in[11];
    const float* W_out     = (const float*)d_in[12];
    const float* gamma     = (const float*)d_in[13];
    const float* beta      = (const float*)d_in[14];
    const float* W_phase   = (const float*)d_in[15];
    float* out = (float*)d_out;

    float* pxz;  cudaGetSymbolAddress((void**)&pxz,  g_xz);
    float* pxps; cudaGetSymbolAddress((void**)&pxps, g_xps);
    float* po;   cudaGetSymbolAddress((void**)&po,   g_o);
    uint32_t* pxperm;  cudaGetSymbolAddress((void**)&pxperm,  g_xperm);
    uint32_t* pwinp;   cudaGetSymbolAddress((void**)&pwinp,   g_winp);
    uint32_t* pxmperm; cudaGetSymbolAddress((void**)&pxmperm, g_xmperm);
    uint32_t* pwxp;    cudaGetSymbolAddress((void**)&pwxp,    g_wxp);
    uint32_t* pyperm;  cudaGetSymbolAddress((void**)&pyperm,  g_yperm);
    uint32_t* pwoutp;  cudaGetSymbolAddress((void**)&pwoutp,  g_woutp);

    /* 0) all operand permutes in one launch */
    perm_all_kernel<<<PERM_NA + PERM_NB1 + PERM_NB2 + PERM_NB3, 256>>>(
        x, W_in, W_out, W_x);

    /* 1) xz = x @ W_in : tensor bf16-split, 400 blocks, prefetched */
    gemm_bf16_kernel<16><<<dim3(16, 25, 1), 256>>>(
        pxperm, pwinp, pxz, 2 * DI, DM / 16, 0);

    /* 2) conv + SiLU -> g_xm + fragment-split g_xmperm */
    conv_silu_kernel<<<(MROWS * (DI / 4) + 255) / 256, 256>>>(conv_w, conv_b);

    /* 3) xp slices = x_m @ W_x : splitK=4 (300 blocks), prefetched */
    gemm_bf16_kernel<8><<<dim3(3, 25, XSPLIT), 256>>>(
        pxmperm, pwxp, pxps, XP_P, DI / 16, MROWS * XP_P);

    /* 4) xp slice-sum + phase add + dt + scan-stream pack */
    dt_phase_kernel<<<MROWS / 4, 256>>>(W_dt, b_dt, delta_mag,
                                        cos_phi, sin_phi, W_phase);

    /* 5) selective scan (d-pair warps, 8-step batched reduction) */
    scan_kernel<<<(B_SZ * NDP * 32) / 128, 128>>>(A_log, D_skip);

    /* 6) g_o slices = y @ W_out : splitK=4 (400 blocks), prefetched */
    gemm_bf16_kernel<8><<<dim3(4, 25, OSPLIT), 256>>>(
        pyperm, pwoutp, po, DM, DI / 16, MROWS * DM);

    /* 7) residual + slice-sum + LayerNorm -> out */
    ln_kernel<<<MROWS, DM>>>(x, gamma, beta, out);
}

// round 15
// speedup vs baseline: 1.2323x; 1.2323x over previous
#include <cuda_runtime.h>
#include <cuda_bf16.h>
#include <math.h>
#include <stdint.h>

#define B_SZ 8
#define LSEQ 200
#define DM   256
#define DI   512
#define DS   64
#define DTR  16
#define NB   4
#define MROWS (B_SZ*LSEQ)      /* 1600 */
#define XP_N  (DTR + 2*DS)     /* 144 real columns  */
#define XP_P  192              /* padded stride     */
#define OSPLIT 4               /* splitK for the out GEMM */
#define XSPLIT 4               /* splitK for the xp GEMM  */
#define NDP   (DI/2)           /* 256 d-pairs */
#define SB    4                /* scan reduction batch (R13 winner) */

/* ---------------- scratch (device globals; no runtime allocation) -------- */
__device__ float g_xz [MROWS * 2 * DI];
__device__ float g_xm [MROWS * DI];
__device__ float g_xps[XSPLIT * MROWS * XP_P];   /* xp splitK slices */
__device__ float g_xp [MROWS * XP_P];            /* final xp (+phase) */
__device__ float g_o  [OSPLIT * MROWS * DM];
/* packed scan stream: [(b*NDP+dp)*LSEQ + t] * 8 floats = dt0,dt1,u0,u1,z0,z1 */
__device__ float g_pack[B_SZ * NDP * LSEQ * 8];

/* fragment-ordered bf16 hi/lo operand arrays */
__device__ uint32_t g_xperm [(MROWS/16) * (DM/16) * 32 * 8];   /* A of xz  */
__device__ uint32_t g_winp  [(2*DI/8) * (DM/16) * 32 * 4];     /* B of xz  */
__device__ uint32_t g_xmperm[(MROWS/16) * (DI/16) * 32 * 8];   /* A of xp  */
__device__ uint32_t g_wxp   [(XP_P/8) * (DI/16) * 32 * 4];     /* B of xp  */
__device__ uint32_t g_yperm [(MROWS/16) * (DI/16) * 32 * 8];   /* A of out */
__device__ uint32_t g_woutp [(DM/8) * (DI/16) * 32 * 4];       /* B of out */

__device__ __forceinline__ float softplusf(float x) {
    return x > 20.f ? x : __logf(1.f + __expf(x));
}
__device__ __forceinline__ float siluf(float x) {
    return x / (1.f + __expf(-x));
}
__device__ __forceinline__ float warp_sum(float v) {
#pragma unroll
    for (int o = 16; o; o >>= 1) v += __shfl_xor_sync(0xffffffffu, v, o);
    return v;
}

/* pack (a,b) -> bf16x2 hi + residual bf16x2 lo */
__device__ __forceinline__ void bf16split2(float a, float b,
                                           uint32_t& hi, uint32_t& lo) {
    __nv_bfloat16 ha = __float2bfloat16(a);
    __nv_bfloat16 hb = __float2bfloat16(b);
    float ra = a - __bfloat162float(ha);
    float rb = b - __bfloat162float(hb);
    __nv_bfloat16 la = __float2bfloat16(ra);
    __nv_bfloat16 lb = __float2bfloat16(rb);
    hi = ((uint32_t)*(uint16_t*)&hb << 16) | *(uint16_t*)&ha;
    lo = ((uint32_t)*(uint16_t*)&lb << 16) | *(uint16_t*)&la;
}

/* ---------------- fused operand permute+split ----------------------------- */
__device__ __forceinline__ void aperm_body(const float* __restrict__ A,
                                           uint32_t* __restrict__ Ap,
                                           int j, int M, int K) {
    int KH = K >> 1;
    int m = j / KH, k = (j - m * KH) * 2;
    float2 v = *(const float2*)(A + (size_t)m * K + k);
    uint32_t hi, lo;
    bf16split2(v.x, v.y, hi, lo);
    int KT = K >> 4;
    int mt = m >> 4, kt = k >> 4;
    int lane = (m & 7) * 4 + ((k & 7) >> 1);
    int reg  = ((m >> 3) & 1) + (((k >> 3) & 1) << 1);
    size_t idx = ((((size_t)mt * KT + kt) * 32 + lane) << 3) + reg;
    Ap[idx]     = hi;
    Ap[idx + 4] = lo;
}
__device__ __forceinline__ void bperm_body(const float* __restrict__ B,
                                           uint32_t* __restrict__ Bp,
                                           int j, int K, int ldb, int Nreal) {
    int KH = K >> 1;
    int n = j / KH, k = (j - n * KH) * 2;
    float a = (n < Nreal) ? B[(size_t)k * ldb + n] : 0.f;
    float b = (n < Nreal) ? B[(size_t)(k + 1) * ldb + n] : 0.f;
    uint32_t hi, lo;
    bf16split2(a, b, hi, lo);
    int KT = K >> 4;
    int n8 = n >> 3, kt = k >> 4;
    int lane = (n & 7) * 4 + ((k & 7) >> 1);
    int reg  = (k >> 3) & 1;
    size_t idx = ((((size_t)n8 * KT + kt) * 32 + lane) << 2) + reg;
    Bp[idx]     = hi;
    Bp[idx + 2] = lo;
}

#define PERM_NA  ((MROWS * DM / 2) / 256)        /* 800 */
#define PERM_NB1 ((2 * DI * DM / 2) / 256)       /* 512 */
#define PERM_NB2 ((DM * DI / 2) / 256)           /* 256 */
#define PERM_NB3 ((XP_P * DI / 2) / 256)         /* 192 */

__global__ __launch_bounds__(256) void perm_all_kernel(
    const float* __restrict__ x, const float* __restrict__ W_in,
    const float* __restrict__ W_out, const float* __restrict__ W_x) {
    int bid = blockIdx.x, tid = threadIdx.x;
    if (bid < PERM_NA) {
        aperm_body(x, g_xperm, bid * 256 + tid, MROWS, DM);
    } else if (bid < PERM_NA + PERM_NB1) {
        bperm_body(W_in, g_winp, (bid - PERM_NA) * 256 + tid,
                   DM, 2 * DI, 2 * DI);
    } else if (bid < PERM_NA + PERM_NB1 + PERM_NB2) {
        bperm_body(W_out, g_woutp, (bid - PERM_NA - PERM_NB1) * 256 + tid,
                   DI, DM, DM);
    } else {
        bperm_body(W_x, g_wxp, (bid - PERM_NA - PERM_NB1 - PERM_NB2) * 256 + tid,
                   DI, XP_N, XP_N);
    }
}

/* ------ bf16-split tensor GEMM, warp tile 32x16, register prefetch ------- */
__device__ __forceinline__ void mma_bf16(float* c, const uint32_t* a,
                                         const uint32_t* b) {
    asm volatile(
        "mma.sync.aligned.m16n8k16.row.col.f32.bf16.bf16.f32 "
        "{%0,%1,%2,%3},{%4,%5,%6,%7},{%8,%9},{%0,%1,%2,%3};"
        : "+f"(c[0]), "+f"(c[1]), "+f"(c[2]), "+f"(c[3])
        : "r"(a[0]), "r"(a[1]), "r"(a[2]), "r"(a[3]), "r"(b[0]), "r"(b[1]));
}

template<int NKT>
__global__ __launch_bounds__(256) void gemm_bf16_kernel(
    const uint32_t* __restrict__ Ap, const uint32_t* __restrict__ Bp,
    float* __restrict__ C, int ldc, int KT, int sliceElems)
{
    const int lane   = threadIdx.x & 31;
    const int warpid = threadIdx.x >> 5;
    const int wm = warpid & 1, wn = warpid >> 1;
    const int ktBegin = blockIdx.z * NKT;
    C += (size_t)blockIdx.z * sliceElems;
    const int mt0 = blockIdx.y * 4 + wm * 2;
    const int n80 = blockIdx.x * 8 + wn * 2;

    float acc[2][2][4] = {};
    uint4 ah[2][2], al[2][2], bfr[2][2];

    auto loadk = [&](int kt, int s) {
#pragma unroll
        for (int mt = 0; mt < 2; mt++) {
            const uint32_t* p =
                Ap + ((((size_t)(mt0 + mt) * KT + kt) * 32 + lane) << 3);
            ah[s][mt] = *(const uint4*)p;
            al[s][mt] = *(const uint4*)(p + 4);
        }
#pragma unroll
        for (int nt = 0; nt < 2; nt++)
            bfr[s][nt] = *(const uint4*)(
                Bp + ((((size_t)(n80 + nt) * KT + kt) * 32 + lane) << 2));
    };

    loadk(ktBegin, 0);
#pragma unroll
    for (int kk = 0; kk < NKT; kk++) {
        const int cur = kk & 1;
        if (kk + 1 < NKT) loadk(ktBegin + kk + 1, cur ^ 1);
#pragma unroll
        for (int mt = 0; mt < 2; mt++)
#pragma unroll
            for (int nt = 0; nt < 2; nt++) {
                uint32_t bh[2] = {bfr[cur][nt].x, bfr[cur][nt].y};
                uint32_t bl[2] = {bfr[cur][nt].z, bfr[cur][nt].w};
                mma_bf16(acc[mt][nt], (const uint32_t*)&ah[cur][mt], bh);
                mma_bf16(acc[mt][nt], (const uint32_t*)&ah[cur][mt], bl);
                mma_bf16(acc[mt][nt], (const uint32_t*)&al[cur][mt], bh);
            }
    }

    const int g = lane >> 2, tig = lane & 3;
#pragma unroll
    for (int mt = 0; mt < 2; mt++) {
        int r = (mt0 + mt) * 16 + g;
#pragma unroll
        for (int nt = 0; nt < 2; nt++) {
            int c = (n80 + nt) * 8 + tig * 2;
            *(float2*)&C[(size_t)r * ldc + c] =
                make_float2(acc[mt][nt][0], acc[mt][nt][1]);
            *(float2*)&C[(size_t)(r + 8) * ldc + c] =
                make_float2(acc[mt][nt][2], acc[mt][nt][3]);
        }
    }
}

/* -- depthwise causal conv (k=4) + SiLU, 4 d/thread; emits xm + fragments - */
__global__ __launch_bounds__(256) void conv_silu_kernel(
    const float* __restrict__ conv_w, const float* __restrict__ conv_b) {
    int idx = blockIdx.x * blockDim.x + threadIdx.x;
    if (idx >= MROWS * (DI / 4)) return;
    int d0  = (idx % (DI / 4)) * 4;
    int row = idx / (DI / 4);
    int l = row % LSEQ;
    const float* xzbase = g_xz + (size_t)row * (2 * DI) + d0;

    float4 acc = *(const float4*)(conv_b + d0);
    float4 w0 = *(const float4*)(conv_w + (d0 + 0) * 4);
    float4 w1 = *(const float4*)(conv_w + (d0 + 1) * 4);
    float4 w2 = *(const float4*)(conv_w + (d0 + 2) * 4);
    float4 w3 = *(const float4*)(conv_w + (d0 + 3) * 4);
    const float* wk[4] = {(const float*)&w0, (const float*)&w1,
                          (const float*)&w2, (const float*)&w3};
#pragma unroll
    for (int k = 0; k < 4; k++) {
        int li = l - 3 + k;
        if (li >= 0) {
            float4 xv = *(const float4*)(xzbase + (size_t)(li - l) * (2 * DI));
            acc.x += wk[0][k] * xv.x;
            acc.y += wk[1][k] * xv.y;
            acc.z += wk[2][k] * xv.z;
            acc.w += wk[3][k] * xv.w;
        }
    }
    float4 o;
    o.x = siluf(acc.x); o.y = siluf(acc.y);
    o.z = siluf(acc.z); o.w = siluf(acc.w);
    *(float4*)(g_xm + (size_t)row * DI + d0) = o;

    uint32_t hi0, lo0, hi1, lo1;
    bf16split2(o.x, o.y, hi0, lo0);
    bf16split2(o.z, o.w, hi1, lo1);
    int mt = row >> 4, kt = d0 >> 4;
    int lane0 = (row & 7) * 4 + ((d0 & 7) >> 1);
    int reg   = ((row >> 3) & 1) + (((d0 >> 3) & 1) << 1);
    size_t base = ((((size_t)mt * (DI / 16) + kt) * 32 + lane0) << 3) + reg;
    g_xmperm[base]      = hi0;
    g_xmperm[base + 4]  = lo0;
    g_xmperm[base + 8]  = hi1;
    g_xmperm[base + 12] = lo1;
}

/* --- xp slice-sum + phase-add + dt + scan-stream pack --------------------- */
__global__ __launch_bounds__(256) void dt_phase_kernel(
    const float* __restrict__ W_dt, const float* __restrict__ b_dt,
    const float* __restrict__ delta_mag,
    const float* __restrict__ cosp, const float* __restrict__ sinp,
    const float* __restrict__ Wph) {
    int row = blockIdx.x * 4 + (threadIdx.x >> 6);
    int t64 = threadIdx.x & 63;
    int b = row / LSEQ, l = row % LSEQ;

    float ph[2 * NB];
#pragma unroll
    for (int jb = 0; jb < NB; jb++) {
        ph[jb]      = cosp[(b * NB + jb) * LSEQ + l];
        ph[NB + jb] = sinp[(b * NB + jb) * LSEQ + l];
    }

#pragma unroll
    for (int q = 0; q < 3; q++) {
        int c = t64 + q * 64;
        if (c < XP_N) {
            size_t off = (size_t)row * XP_P + c;
            float s = 0.f;
#pragma unroll
            for (int sl = 0; sl < XSPLIT; sl++)
                s += g_xps[(size_t)sl * MROWS * XP_P + off];
            if (c >= DTR + DS) {
                int n = c - (DTR + DS);
#pragma unroll
                for (int j = 0; j < 2 * NB; j++) s += ph[j] * Wph[j * DS + n];
            }
            g_xp[off] = s;
        }
    }
    __syncthreads();

    int d0 = t64 * 8;
    float dl[DTR];
    {
        const float4* p = (const float4*)(g_xp + (size_t)row * XP_P);
#pragma unroll
        for (int q = 0; q < DTR / 4; q++) {
            float4 v = p[q];
            dl[q * 4 + 0] = v.x; dl[q * 4 + 1] = v.y;
            dl[q * 4 + 2] = v.z; dl[q * 4 + 3] = v.w;
        }
    }
    float4 acc0 = *(const float4*)(b_dt + d0);
    float4 acc1 = *(const float4*)(b_dt + d0 + 4);
#pragma unroll
    for (int r = 0; r < DTR; r++) {
        float4 w0 = *(const float4*)(W_dt + r * DI + d0);
        float4 w1 = *(const float4*)(W_dt + r * DI + d0 + 4);
        acc0.x += dl[r] * w0.x;  acc0.y += dl[r] * w0.y;
        acc0.z += dl[r] * w0.z;  acc0.w += dl[r] * w0.w;
        acc1.x += dl[r] * w1.x;  acc1.y += dl[r] * w1.y;
        acc1.z += dl[r] * w1.z;  acc1.w += dl[r] * w1.w;
    }
    float dmm = 0.25f * (delta_mag[(b * NB + 0) * LSEQ + l] +
                         delta_mag[(b * NB + 1) * LSEQ + l] +
                         delta_mag[(b * NB + 2) * LSEQ + l] +
                         delta_mag[(b * NB + 3) * LSEQ + l]);
    float scale = 1.f + softplusf(dmm);
    float dt8[8];
    dt8[0] = softplusf(acc0.x) * scale;  dt8[1] = softplusf(acc0.y) * scale;
    dt8[2] = softplusf(acc0.z) * scale;  dt8[3] = softplusf(acc0.w) * scale;
    dt8[4] = softplusf(acc1.x) * scale;  dt8[5] = softplusf(acc1.y) * scale;
    dt8[6] = softplusf(acc1.z) * scale;  dt8[7] = softplusf(acc1.w) * scale;

    float4 u0 = *(const float4*)(g_xm + (size_t)row * DI + d0);
    float4 u1 = *(const float4*)(g_xm + (size_t)row * DI + d0 + 4);
    float4 z0 = *(const float4*)(g_xz + (size_t)row * (2 * DI) + DI + d0);
    float4 z1 = *(const float4*)(g_xz + (size_t)row * (2 * DI) + DI + d0 + 4);
    float uu[8] = {u0.x, u0.y, u0.z, u0.w, u1.x, u1.y, u1.z, u1.w};
    float zz[8] = {z0.x, z0.y, z0.z, z0.w, z1.x, z1.y, z1.z, z1.w};
    int dpBase = (d0 >> 1);
#pragma unroll
    for (int p = 0; p < 4; p++) {
        int dp = dpBase + p;
        float* pk = g_pack + (((size_t)(b * NDP + dp)) * LSEQ + l) * 8;
        *(float4*)pk = make_float4(dt8[2*p], dt8[2*p+1], uu[2*p], uu[2*p+1]);
        *(float2*)(pk + 4) = make_float2(zz[2*p], zz[2*p+1]);
    }
}

/* -- selective scan: warp per (b,d-pair); 4-step batched reduction -------- */
__global__ __launch_bounds__(128) void scan_kernel(
    const float* __restrict__ A_log, const float* __restrict__ D_skip) {
    int warp = (blockIdx.x * blockDim.x + threadIdx.x) >> 5;
    int lane = threadIdx.x & 31;
    int b  = warp >> 8;
    int dp = warp & 255;
    int d0 = dp * 2;

    float2 a0 = *(const float2*)(A_log + (size_t)d0 * DS + 2 * lane);
    float2 a1 = *(const float2*)(A_log + (size_t)(d0 + 1) * DS + 2 * lane);
    float A00 = -__expf(a0.x), A01 = -__expf(a0.y);
    float A10 = -__expf(a1.x), A11 = -__expf(a1.y);
    float2 Dd = *(const float2*)(D_skip + d0);

    float h00 = 0.f, h01 = 0.f, h10 = 0.f, h11 = 0.f;

    const float* xpB = g_xp + (size_t)(b * LSEQ) * XP_P + DTR + 2 * lane;
    const float* pk  = g_pack + ((size_t)(b * NDP + dp)) * LSEQ * 8;

    const int half = lane >> 4;
    const bool isL0  = (lane == 0);
    const bool isL16 = (lane == 16);
    const int rowBase = b * LSEQ;
    const int ktd   = d0 >> 4;
    const int lane_c = (d0 & 7) >> 1;
    const int reg_c  = ((d0 >> 3) & 1) << 1;

    float2 Bs[SB], Cs[SB], zs[SB];
    float4 ps[SB];
#pragma unroll
    for (int s = 0; s < SB; s++) {
        const float* p = xpB + (size_t)s * XP_P;
        Bs[s] = *(const float2*)(p);
        Cs[s] = *(const float2*)(p + DS);
        ps[s] = *(const float4*)(pk + s * 8);
        zs[s] = *(const float2*)(pk + s * 8 + 4);
    }

#pragma unroll 1
    for (int t = 0; t < LSEQ; t += SB) {
        float p0s[SB], p1s[SB];
        float2 zsv[SB];
        /* phase 1: recurrence for SB steps + prefetch; fold u*D on lanes 0/16 */
#pragma unroll
        for (int s = 0; s < SB; s++) {
            float4 pv = ps[s];
            float2 z = zs[s], Bv = Bs[s], Cv = Cs[s];
            int tn = t + SB + s;
            if (tn < LSEQ) {
                const float* p = xpB + (size_t)tn * XP_P;
                Bs[s] = *(const float2*)(p);
                Cs[s] = *(const float2*)(p + DS);
                ps[s] = *(const float4*)(pk + (size_t)tn * 8);
                zs[s] = *(const float2*)(pk + (size_t)tn * 8 + 4);
            }
            float e00 = __expf(pv.x * A00), e01 = __expf(pv.x * A01);
            float e10 = __expf(pv.y * A10), e11 = __expf(pv.y * A11);
            float du0 = pv.x * pv.z, du1 = pv.y * pv.w;
            h00 = fmaf(e00, h00, du0 * Bv.x);
            h01 = fmaf(e01, h01, du0 * Bv.y);
            h10 = fmaf(e10, h10, du1 * Bv.x);
            h11 = fmaf(e11, h11, du1 * Bv.y);
            p0s[s] = fmaf(h01, Cv.y, h00 * Cv.x);
            p1s[s] = fmaf(h11, Cv.y, h10 * Cv.x);
            if (isL0)  p0s[s] += pv.z * Dd.x;   /* fold u0*D0 */
            if (isL16) p1s[s] += pv.w * Dd.y;   /* fold u1*D1 */
            zsv[s] = z;
        }
        /* phase 2: SB independent butterflies, pipelined rounds */
        float v[SB];
#pragma unroll
        for (int s = 0; s < SB; s++) {
            float q0 = __shfl_xor_sync(0xffffffffu, p0s[s], 16);
            float q1 = __shfl_xor_sync(0xffffffffu, p1s[s], 16);
            v[s] = half ? (p1s[s] + q1) : (p0s[s] + q0);
        }
#pragma unroll
        for (int o = 8; o; o >>= 1) {
#pragma unroll
            for (int s = 0; s < SB; s++)
                v[s] += __shfl_xor_sync(0xffffffffu, v[s], o);
        }
        float v1[SB];
#pragma unroll
        for (int s = 0; s < SB; s++)
            v1[s] = __shfl_sync(0xffffffffu, v[s], 16);
        /* phase 3: stores (lane 0, off critical path) */
        if (isL0) {
#pragma unroll
            for (int s = 0; s < SB; s++) {
                float y0 = v[s]  * siluf(zsv[s].x);
                float y1 = v1[s] * siluf(zsv[s].y);
                int m = rowBase + t + s;
                int lanep = (m & 7) * 4 + lane_c;
                int reg   = ((m >> 3) & 1) + reg_c;
                size_t idx = ((((size_t)(m >> 4) * (DI / 16) + ktd) * 32
                               + lanep) << 3) + reg;
                uint32_t hi, lo;
                bf16split2(y0, y1, hi, lo);
                g_yperm[idx]     = hi;
                g_yperm[idx + 4] = lo;
            }
        }
    }
}

/* --------- residual add + sum of splitK slices + LayerNorm --------------- */
__global__ void ln_kernel(const float* __restrict__ x,
                          const float* __restrict__ gamma,
                          const float* __restrict__ beta,
                          float* __restrict__ out) {
    int row = blockIdx.x;
    int c = threadIdx.x;
    float v = x[(size_t)row * DM + c];
#pragma unroll
    for (int s = 0; s < OSPLIT; s++)
        v += g_o[(size_t)s * MROWS * DM + (size_t)row * DM + c];

    float sum  = warp_sum(v);
    float sum2 = warp_sum(v * v);
    __shared__ float ws[8], ws2[8];
    int w = c >> 5, lane = c & 31;
    if (lane == 0) { ws[w] = sum; ws2[w] = sum2; }
    __syncthreads();
    float tot = 0.f, tot2 = 0.f;
#pragma unroll
    for (int i = 0; i < 8; i++) { tot += ws[i]; tot2 += ws2[i]; }
    float mu  = tot * (1.f / DM);
    float var = tot2 * (1.f / DM) - mu * mu;
    out[(size_t)row * DM + c] = (v - mu) * rsqrtf(var + 1e-12f) * gamma[c] + beta[c];
}

/* ---------------- launch --------------------------------------------------*/
extern "C" void kernel_launch(void* const* d_in, const int* in_sizes, int n_in,
                              void* d_out, int out_size) {
    const float* x         = (const float*)d_in[0];
    const float* cos_phi   = (const float*)d_in[1];
    const float* sin_phi   = (const float*)d_in[2];
    const float* delta_mag = (const float*)d_in[3];
    const float* W_in      = (const float*)d_in[4];
    const float* conv_w    = (const float*)d_in[5];
    const float* conv_b    = (const float*)d_in[6];
    const float* W_x       = (const float*)d_in[7];
    const float* W_dt      = (const float*)d_in[8];
    const float* b_dt      = (const float*)d_in[9];
    const float* A_log     = (const float*)d_in[10];
    const float* D_skip    = (const float*)d_in[11];
    const float* W_out     = (const float*)d_in[12];
    const float* gamma     = (const float*)d_in[13];
    const float* beta      = (const float*)d_in[14];
    const float* W_phase   = (const float*)d_in[15];
    float* out = (float*)d_out;

    float* pxz;  cudaGetSymbolAddress((void**)&pxz,  g_xz);
    float* pxps; cudaGetSymbolAddress((void**)&pxps, g_xps);
    float* po;   cudaGetSymbolAddress((void**)&po,   g_o);
    uint32_t* pxperm;  cudaGetSymbolAddress((void**)&pxperm,  g_xperm);
    uint32_t* pwinp;   cudaGetSymbolAddress((void**)&pwinp,   g_winp);
    uint32_t* pxmperm; cudaGetSymbolAddress((void**)&pxmperm, g_xmperm);
    uint32_t* pwxp;    cudaGetSymbolAddress((void**)&pwxp,    g_wxp);
    uint32_t* pyperm;  cudaGetSymbolAddress((void**)&pyperm,  g_yperm);
    uint32_t* pwoutp;  cudaGetSymbolAddress((void**)&pwoutp,  g_woutp);

    /* 0) all operand permutes in one launch */
    perm_all_kernel<<<PERM_NA + PERM_NB1 + PERM_NB2 + PERM_NB3, 256>>>(
        x, W_in, W_out, W_x);

    /* 1) xz = x @ W_in : tensor bf16-split, 400 blocks, prefetched */
    gemm_bf16_kernel<16><<<dim3(16, 25, 1), 256>>>(
        pxperm, pwinp, pxz, 2 * DI, DM / 16, 0);

    /* 2) conv + SiLU -> g_xm + fragment-split g_xmperm */
    conv_silu_kernel<<<(MROWS * (DI / 4) + 255) / 256, 256>>>(conv_w, conv_b);

    /* 3) xp slices = x_m @ W_x : splitK=4 (300 blocks), prefetched */
    gemm_bf16_kernel<8><<<dim3(3, 25, XSPLIT), 256>>>(
        pxmperm, pwxp, pxps, XP_P, DI / 16, MROWS * XP_P);

    /* 4) xp slice-sum + phase add + dt + scan-stream pack */
    dt_phase_kernel<<<MROWS / 4, 256>>>(W_dt, b_dt, delta_mag,
                                        cos_phi, sin_phi, W_phase);

    /* 5) selective scan (d-pair warps, 4-step batched reduction) */
    scan_kernel<<<(B_SZ * NDP * 32) / 128, 128>>>(A_log, D_skip);

    /* 6) g_o slices = y @ W_out : splitK=4 (400 blocks), prefetched */
    gemm_bf16_kernel<8><<<dim3(4, 25, OSPLIT), 256>>>(
        pyperm, pwoutp, po, DM, DI / 16, MROWS * DM);

    /* 7) residual + slice-sum + LayerNorm -> out */
    ln_kernel<<<MROWS, DM>>>(x, gamma, beta, out);
}

// round 16
// speedup vs baseline: 1.3691x; 1.1110x over previous
#include <cuda_runtime.h>
#include <cuda_bf16.h>
#include <math.h>
#include <stdint.h>

#define B_SZ 8
#define LSEQ 200
#define DM   256
#define DI   512
#define DS   64
#define DTR  16
#define NB   4
#define MROWS (B_SZ*LSEQ)      /* 1600 */
#define XP_N  (DTR + 2*DS)     /* 144 real columns  */
#define XP_P  192              /* padded stride     */
#define OSPLIT 4               /* splitK for the out GEMM */
#define XSPLIT 4               /* splitK for the xp GEMM  */
#define NDP   (DI/2)           /* 256 d-pairs */

/* ---------------- scratch (device globals; no runtime allocation) -------- */
__device__ float g_xz [MROWS * 2 * DI];
__device__ float g_xm [MROWS * DI];
__device__ float g_xps[XSPLIT * MROWS * XP_P];   /* xp splitK slices */
__device__ float g_xp [MROWS * XP_P];            /* final xp (+phase) */
__device__ float g_o  [OSPLIT * MROWS * DM];
/* packed scan stream: [(b*NDP+dp)*LSEQ + t] * 8 floats = dt0,dt1,u0,u1,z0,z1 */
__device__ float g_pack[B_SZ * NDP * LSEQ * 8];

/* fragment-ordered bf16 hi/lo operand arrays */
__device__ uint32_t g_xperm [(MROWS/16) * (DM/16) * 32 * 8];   /* A of xz  */
__device__ uint32_t g_winp  [(2*DI/8) * (DM/16) * 32 * 4];     /* B of xz  */
__device__ uint32_t g_xmperm[(MROWS/16) * (DI/16) * 32 * 8];   /* A of xp  */
__device__ uint32_t g_wxp   [(XP_P/8) * (DI/16) * 32 * 4];     /* B of xp  */
__device__ uint32_t g_yperm [(MROWS/16) * (DI/16) * 32 * 8];   /* A of out */
__device__ uint32_t g_woutp [(DM/8) * (DI/16) * 32 * 4];       /* B of out */

__device__ __forceinline__ float softplusf(float x) {
    return x > 20.f ? x : __logf(1.f + __expf(x));
}
__device__ __forceinline__ float siluf(float x) {
    return x / (1.f + __expf(-x));
}
__device__ __forceinline__ float warp_sum(float v) {
#pragma unroll
    for (int o = 16; o; o >>= 1) v += __shfl_xor_sync(0xffffffffu, v, o);
    return v;
}

/* pack (a,b) -> bf16x2 hi + residual bf16x2 lo */
__device__ __forceinline__ void bf16split2(float a, float b,
                                           uint32_t& hi, uint32_t& lo) {
    __nv_bfloat16 ha = __float2bfloat16(a);
    __nv_bfloat16 hb = __float2bfloat16(b);
    float ra = a - __bfloat162float(ha);
    float rb = b - __bfloat162float(hb);
    __nv_bfloat16 la = __float2bfloat16(ra);
    __nv_bfloat16 lb = __float2bfloat16(rb);
    hi = ((uint32_t)*(uint16_t*)&hb << 16) | *(uint16_t*)&ha;
    lo = ((uint32_t)*(uint16_t*)&lb << 16) | *(uint16_t*)&la;
}

/* ---------------- fused operand permute+split ----------------------------- */
__device__ __forceinline__ void aperm_body(const float* __restrict__ A,
                                           uint32_t* __restrict__ Ap,
                                           int j, int M, int K) {
    int KH = K >> 1;
    int m = j / KH, k = (j - m * KH) * 2;
    float2 v = *(const float2*)(A + (size_t)m * K + k);
    uint32_t hi, lo;
    bf16split2(v.x, v.y, hi, lo);
    int KT = K >> 4;
    int mt = m >> 4, kt = k >> 4;
    int lane = (m & 7) * 4 + ((k & 7) >> 1);
    int reg  = ((m >> 3) & 1) + (((k >> 3) & 1) << 1);
    size_t idx = ((((size_t)mt * KT + kt) * 32 + lane) << 3) + reg;
    Ap[idx]     = hi;
    Ap[idx + 4] = lo;
}
__device__ __forceinline__ void bperm_body(const float* __restrict__ B,
                                           uint32_t* __restrict__ Bp,
                                           int j, int K, int ldb, int Nreal) {
    int KH = K >> 1;
    int n = j / KH, k = (j - n * KH) * 2;
    float a = (n < Nreal) ? B[(size_t)k * ldb + n] : 0.f;
    float b = (n < Nreal) ? B[(size_t)(k + 1) * ldb + n] : 0.f;
    uint32_t hi, lo;
    bf16split2(a, b, hi, lo);
    int KT = K >> 4;
    int n8 = n >> 3, kt = k >> 4;
    int lane = (n & 7) * 4 + ((k & 7) >> 1);
    int reg  = (k >> 3) & 1;
    size_t idx = ((((size_t)n8 * KT + kt) * 32 + lane) << 2) + reg;
    Bp[idx]     = hi;
    Bp[idx + 2] = lo;
}

#define PERM_NA  ((MROWS * DM / 2) / 256)        /* 800 */
#define PERM_NB1 ((2 * DI * DM / 2) / 256)       /* 512 */
#define PERM_NB2 ((DM * DI / 2) / 256)           /* 256 */
#define PERM_NB3 ((XP_P * DI / 2) / 256)         /* 192 */

__global__ __launch_bounds__(256) void perm_all_kernel(
    const float* __restrict__ x, const float* __restrict__ W_in,
    const float* __restrict__ W_out, const float* __restrict__ W_x) {
    int bid = blockIdx.x, tid = threadIdx.x;
    if (bid < PERM_NA) {
        aperm_body(x, g_xperm, bid * 256 + tid, MROWS, DM);
    } else if (bid < PERM_NA + PERM_NB1) {
        bperm_body(W_in, g_winp, (bid - PERM_NA) * 256 + tid,
                   DM, 2 * DI, 2 * DI);
    } else if (bid < PERM_NA + PERM_NB1 + PERM_NB2) {
        bperm_body(W_out, g_woutp, (bid - PERM_NA - PERM_NB1) * 256 + tid,
                   DI, DM, DM);
    } else {
        bperm_body(W_x, g_wxp, (bid - PERM_NA - PERM_NB1 - PERM_NB2) * 256 + tid,
                   DI, XP_N, XP_N);
    }
}

/* ------ bf16-split tensor GEMM, warp tile 32x16, register prefetch ------- */
__device__ __forceinline__ void mma_bf16(float* c, const uint32_t* a,
                                         const uint32_t* b) {
    asm volatile(
        "mma.sync.aligned.m16n8k16.row.col.f32.bf16.bf16.f32 "
        "{%0,%1,%2,%3},{%4,%5,%6,%7},{%8,%9},{%0,%1,%2,%3};"
        : "+f"(c[0]), "+f"(c[1]), "+f"(c[2]), "+f"(c[3])
        : "r"(a[0]), "r"(a[1]), "r"(a[2]), "r"(a[3]), "r"(b[0]), "r"(b[1]));
}

template<int NKT>
__global__ __launch_bounds__(256) void gemm_bf16_kernel(
    const uint32_t* __restrict__ Ap, const uint32_t* __restrict__ Bp,
    float* __restrict__ C, int ldc, int KT, int sliceElems)
{
    const int lane   = threadIdx.x & 31;
    const int warpid = threadIdx.x >> 5;
    const int wm = warpid & 1, wn = warpid >> 1;
    const int ktBegin = blockIdx.z * NKT;
    C += (size_t)blockIdx.z * sliceElems;
    const int mt0 = blockIdx.y * 4 + wm * 2;
    const int n80 = blockIdx.x * 8 + wn * 2;

    float acc[2][2][4] = {};
    uint4 ah[2][2], al[2][2], bfr[2][2];

    auto loadk = [&](int kt, int s) {
#pragma unroll
        for (int mt = 0; mt < 2; mt++) {
            const uint32_t* p =
                Ap + ((((size_t)(mt0 + mt) * KT + kt) * 32 + lane) << 3);
            ah[s][mt] = *(const uint4*)p;
            al[s][mt] = *(const uint4*)(p + 4);
        }
#pragma unroll
        for (int nt = 0; nt < 2; nt++)
            bfr[s][nt] = *(const uint4*)(
                Bp + ((((size_t)(n80 + nt) * KT + kt) * 32 + lane) << 2));
    };

    loadk(ktBegin, 0);
#pragma unroll
    for (int kk = 0; kk < NKT; kk++) {
        const int cur = kk & 1;
        if (kk + 1 < NKT) loadk(ktBegin + kk + 1, cur ^ 1);
#pragma unroll
        for (int mt = 0; mt < 2; mt++)
#pragma unroll
            for (int nt = 0; nt < 2; nt++) {
                uint32_t bh[2] = {bfr[cur][nt].x, bfr[cur][nt].y};
                uint32_t bl[2] = {bfr[cur][nt].z, bfr[cur][nt].w};
                mma_bf16(acc[mt][nt], (const uint32_t*)&ah[cur][mt], bh);
                mma_bf16(acc[mt][nt], (const uint32_t*)&ah[cur][mt], bl);
                mma_bf16(acc[mt][nt], (const uint32_t*)&al[cur][mt], bh);
            }
    }

    const int g = lane >> 2, tig = lane & 3;
#pragma unroll
    for (int mt = 0; mt < 2; mt++) {
        int r = (mt0 + mt) * 16 + g;
#pragma unroll
        for (int nt = 0; nt < 2; nt++) {
            int c = (n80 + nt) * 8 + tig * 2;
            *(float2*)&C[(size_t)r * ldc + c] =
                make_float2(acc[mt][nt][0], acc[mt][nt][1]);
            *(float2*)&C[(size_t)(r + 8) * ldc + c] =
                make_float2(acc[mt][nt][2], acc[mt][nt][3]);
        }
    }
}

/* -- depthwise causal conv (k=4) + SiLU, 4 d/thread; emits xm + fragments - */
__global__ __launch_bounds__(256) void conv_silu_kernel(
    const float* __restrict__ conv_w, const float* __restrict__ conv_b) {
    int idx = blockIdx.x * blockDim.x + threadIdx.x;
    if (idx >= MROWS * (DI / 4)) return;
    int d0  = (idx % (DI / 4)) * 4;
    int row = idx / (DI / 4);
    int l = row % LSEQ;
    const float* xzbase = g_xz + (size_t)row * (2 * DI) + d0;

    float4 acc = *(const float4*)(conv_b + d0);
    float4 w0 = *(const float4*)(conv_w + (d0 + 0) * 4);
    float4 w1 = *(const float4*)(conv_w + (d0 + 1) * 4);
    float4 w2 = *(const float4*)(conv_w + (d0 + 2) * 4);
    float4 w3 = *(const float4*)(conv_w + (d0 + 3) * 4);
    const float* wk[4] = {(const float*)&w0, (const float*)&w1,
                          (const float*)&w2, (const float*)&w3};
#pragma unroll
    for (int k = 0; k < 4; k++) {
        int li = l - 3 + k;
        if (li >= 0) {
            float4 xv = *(const float4*)(xzbase + (size_t)(li - l) * (2 * DI));
            acc.x += wk[0][k] * xv.x;
            acc.y += wk[1][k] * xv.y;
            acc.z += wk[2][k] * xv.z;
            acc.w += wk[3][k] * xv.w;
        }
    }
    float4 o;
    o.x = siluf(acc.x); o.y = siluf(acc.y);
    o.z = siluf(acc.z); o.w = siluf(acc.w);
    *(float4*)(g_xm + (size_t)row * DI + d0) = o;

    uint32_t hi0, lo0, hi1, lo1;
    bf16split2(o.x, o.y, hi0, lo0);
    bf16split2(o.z, o.w, hi1, lo1);
    int mt = row >> 4, kt = d0 >> 4;
    int lane0 = (row & 7) * 4 + ((d0 & 7) >> 1);
    int reg   = ((row >> 3) & 1) + (((d0 >> 3) & 1) << 1);
    size_t base = ((((size_t)mt * (DI / 16) + kt) * 32 + lane0) << 3) + reg;
    g_xmperm[base]      = hi0;
    g_xmperm[base + 4]  = lo0;
    g_xmperm[base + 8]  = hi1;
    g_xmperm[base + 12] = lo1;
}

/* --- xp slice-sum + phase-add + dt + scan-stream pack --------------------- */
__global__ __launch_bounds__(256) void dt_phase_kernel(
    const float* __restrict__ W_dt, const float* __restrict__ b_dt,
    const float* __restrict__ delta_mag,
    const float* __restrict__ cosp, const float* __restrict__ sinp,
    const float* __restrict__ Wph) {
    int row = blockIdx.x * 4 + (threadIdx.x >> 6);
    int t64 = threadIdx.x & 63;
    int b = row / LSEQ, l = row % LSEQ;

    float ph[2 * NB];
#pragma unroll
    for (int jb = 0; jb < NB; jb++) {
        ph[jb]      = cosp[(b * NB + jb) * LSEQ + l];
        ph[NB + jb] = sinp[(b * NB + jb) * LSEQ + l];
    }

#pragma unroll
    for (int q = 0; q < 3; q++) {
        int c = t64 + q * 64;
        if (c < XP_N) {
            size_t off = (size_t)row * XP_P + c;
            float s = 0.f;
#pragma unroll
            for (int sl = 0; sl < XSPLIT; sl++)
                s += g_xps[(size_t)sl * MROWS * XP_P + off];
            if (c >= DTR + DS) {
                int n = c - (DTR + DS);
#pragma unroll
                for (int j = 0; j < 2 * NB; j++) s += ph[j] * Wph[j * DS + n];
            }
            g_xp[off] = s;
        }
    }
    __syncthreads();

    int d0 = t64 * 8;
    float dl[DTR];
    {
        const float4* p = (const float4*)(g_xp + (size_t)row * XP_P);
#pragma unroll
        for (int q = 0; q < DTR / 4; q++) {
            float4 v = p[q];
            dl[q * 4 + 0] = v.x; dl[q * 4 + 1] = v.y;
            dl[q * 4 + 2] = v.z; dl[q * 4 + 3] = v.w;
        }
    }
    float4 acc0 = *(const float4*)(b_dt + d0);
    float4 acc1 = *(const float4*)(b_dt + d0 + 4);
#pragma unroll
    for (int r = 0; r < DTR; r++) {
        float4 w0 = *(const float4*)(W_dt + r * DI + d0);
        float4 w1 = *(const float4*)(W_dt + r * DI + d0 + 4);
        acc0.x += dl[r] * w0.x;  acc0.y += dl[r] * w0.y;
        acc0.z += dl[r] * w0.z;  acc0.w += dl[r] * w0.w;
        acc1.x += dl[r] * w1.x;  acc1.y += dl[r] * w1.y;
        acc1.z += dl[r] * w1.z;  acc1.w += dl[r] * w1.w;
    }
    float dmm = 0.25f * (delta_mag[(b * NB + 0) * LSEQ + l] +
                         delta_mag[(b * NB + 1) * LSEQ + l] +
                         delta_mag[(b * NB + 2) * LSEQ + l] +
                         delta_mag[(b * NB + 3) * LSEQ + l]);
    float scale = 1.f + softplusf(dmm);
    float dt8[8];
    dt8[0] = softplusf(acc0.x) * scale;  dt8[1] = softplusf(acc0.y) * scale;
    dt8[2] = softplusf(acc0.z) * scale;  dt8[3] = softplusf(acc0.w) * scale;
    dt8[4] = softplusf(acc1.x) * scale;  dt8[5] = softplusf(acc1.y) * scale;
    dt8[6] = softplusf(acc1.z) * scale;  dt8[7] = softplusf(acc1.w) * scale;

    float4 u0 = *(const float4*)(g_xm + (size_t)row * DI + d0);
    float4 u1 = *(const float4*)(g_xm + (size_t)row * DI + d0 + 4);
    float4 z0 = *(const float4*)(g_xz + (size_t)row * (2 * DI) + DI + d0);
    float4 z1 = *(const float4*)(g_xz + (size_t)row * (2 * DI) + DI + d0 + 4);
    float uu[8] = {u0.x, u0.y, u0.z, u0.w, u1.x, u1.y, u1.z, u1.w};
    float zz[8] = {z0.x, z0.y, z0.z, z0.w, z1.x, z1.y, z1.z, z1.w};
    int dpBase = (d0 >> 1);
#pragma unroll
    for (int p = 0; p < 4; p++) {
        int dp = dpBase + p;
        float* pk = g_pack + (((size_t)(b * NDP + dp)) * LSEQ + l) * 8;
        *(float4*)pk = make_float4(dt8[2*p], dt8[2*p+1], uu[2*p], uu[2*p+1]);
        *(float2*)(pk + 4) = make_float2(zz[2*p], zz[2*p+1]);
    }
}

/* -- selective scan: warp per (b,d-pair); 4-step batched reduction (R13) -- */
__global__ __launch_bounds__(128) void scan_kernel(
    const float* __restrict__ A_log, const float* __restrict__ D_skip) {
    int warp = (blockIdx.x * blockDim.x + threadIdx.x) >> 5;
    int lane = threadIdx.x & 31;
    int b  = warp >> 8;
    int dp = warp & 255;
    int d0 = dp * 2;

    float2 a0 = *(const float2*)(A_log + (size_t)d0 * DS + 2 * lane);
    float2 a1 = *(const float2*)(A_log + (size_t)(d0 + 1) * DS + 2 * lane);
    float A00 = -__expf(a0.x), A01 = -__expf(a0.y);
    float A10 = -__expf(a1.x), A11 = -__expf(a1.y);
    float2 Dd = *(const float2*)(D_skip + d0);

    float h00 = 0.f, h01 = 0.f, h10 = 0.f, h11 = 0.f;

    const float* xpB = g_xp + (size_t)(b * LSEQ) * XP_P + DTR + 2 * lane;
    const float* pk  = g_pack + ((size_t)(b * NDP + dp)) * LSEQ * 8;

    const int half = lane >> 4;
    const int rowBase = b * LSEQ;
    const int ktd   = d0 >> 4;
    const int lane_c = (d0 & 7) >> 1;
    const int reg_c  = ((d0 >> 3) & 1) << 1;

    float2 Bs[4], Cs[4], zs[4];
    float4 ps[4];
#pragma unroll
    for (int s = 0; s < 4; s++) {
        const float* p = xpB + (size_t)s * XP_P;
        Bs[s] = *(const float2*)(p);
        Cs[s] = *(const float2*)(p + DS);
        ps[s] = *(const float4*)(pk + s * 8);
        zs[s] = *(const float2*)(pk + s * 8 + 4);
    }

#pragma unroll 1
    for (int t = 0; t < LSEQ; t += 4) {
        float p0s[4], p1s[4];
        float2 usv[4], zsv[4];
        /* phase 1: recurrence for 4 steps (fast FMA chains) + prefetch */
#pragma unroll
        for (int s = 0; s < 4; s++) {
            float4 pv = ps[s];
            float2 z = zs[s], Bv = Bs[s], Cv = Cs[s];
            int tn = t + 4 + s;
            if (tn < LSEQ) {
                const float* p = xpB + (size_t)tn * XP_P;
                Bs[s] = *(const float2*)(p);
                Cs[s] = *(const float2*)(p + DS);
                ps[s] = *(const float4*)(pk + (size_t)tn * 8);
                zs[s] = *(const float2*)(pk + (size_t)tn * 8 + 4);
            }
            float e00 = __expf(pv.x * A00), e01 = __expf(pv.x * A01);
            float e10 = __expf(pv.y * A10), e11 = __expf(pv.y * A11);
            float du0 = pv.x * pv.z, du1 = pv.y * pv.w;
            h00 = fmaf(e00, h00, du0 * Bv.x);
            h01 = fmaf(e01, h01, du0 * Bv.y);
            h10 = fmaf(e10, h10, du1 * Bv.x);
            h11 = fmaf(e11, h11, du1 * Bv.y);
            p0s[s] = fmaf(h01, Cv.y, h00 * Cv.x);
            p1s[s] = fmaf(h11, Cv.y, h10 * Cv.x);
            usv[s] = make_float2(pv.z, pv.w);
            zsv[s] = z;
        }
        /* phase 2: batched reductions — 4 independent butterflies */
        float v[4];
#pragma unroll
        for (int s = 0; s < 4; s++) {
            float q0 = __shfl_xor_sync(0xffffffffu, p0s[s], 16);
            float q1 = __shfl_xor_sync(0xffffffffu, p1s[s], 16);
            v[s] = half ? (p1s[s] + q1) : (p0s[s] + q0);
        }
#pragma unroll
        for (int o = 8; o; o >>= 1) {
#pragma unroll
            for (int s = 0; s < 4; s++)
                v[s] += __shfl_xor_sync(0xffffffffu, v[s], o);
        }
        float v1[4];
#pragma unroll
        for (int s = 0; s < 4; s++)
            v1[s] = __shfl_sync(0xffffffffu, v[s], 16);
        /* phase 3: stores (lane 0, off critical path) */
        if (lane == 0) {
#pragma unroll
            for (int s = 0; s < 4; s++) {
                float y0 = (v[s]  + usv[s].x * Dd.x) * siluf(zsv[s].x);
                float y1 = (v1[s] + usv[s].y * Dd.y) * siluf(zsv[s].y);
                int m = rowBase + t + s;
                int lanep = (m & 7) * 4 + lane_c;
                int reg   = ((m >> 3) & 1) + reg_c;
                size_t idx = ((((size_t)(m >> 4) * (DI / 16) + ktd) * 32
                               + lanep) << 3) + reg;
                uint32_t hi, lo;
                bf16split2(y0, y1, hi, lo);
                g_yperm[idx]     = hi;
                g_yperm[idx + 4] = lo;
            }
        }
    }
}

/* --------- residual add + sum of splitK slices + LayerNorm --------------- */
__global__ void ln_kernel(const float* __restrict__ x,
                          const float* __restrict__ gamma,
                          const float* __restrict__ beta,
                          float* __restrict__ out) {
    int row = blockIdx.x;
    int c = threadIdx.x;
    float v = x[(size_t)row * DM + c];
#pragma unroll
    for (int s = 0; s < OSPLIT; s++)
        v += g_o[(size_t)s * MROWS * DM + (size_t)row * DM + c];

    float sum  = warp_sum(v);
    float sum2 = warp_sum(v * v);
    __shared__ float ws[8], ws2[8];
    int w = c >> 5, lane = c & 31;
    if (lane == 0) { ws[w] = sum; ws2[w] = sum2; }
    __syncthreads();
    float tot = 0.f, tot2 = 0.f;
#pragma unroll
    for (int i = 0; i < 8; i++) { tot += ws[i]; tot2 += ws2[i]; }
    float mu  = tot * (1.f / DM);
    float var = tot2 * (1.f / DM) - mu * mu;
    out[(size_t)row * DM + c] = (v - mu) * rsqrtf(var + 1e-12f) * gamma[c] + beta[c];
}

/* ---------------- launch --------------------------------------------------*/
extern "C" void kernel_launch(void* const* d_in, const int* in_sizes, int n_in,
                              void* d_out, int out_size) {
    const float* x         = (const float*)d_in[0];
    const float* cos_phi   = (const float*)d_in[1];
    const float* sin_phi   = (const float*)d_in[2];
    const float* delta_mag = (const float*)d_in[3];
    const float* W_in      = (const float*)d_in[4];
    const float* conv_w    = (const float*)d_in[5];
    const float* conv_b    = (const float*)d_in[6];
    const float* W_x       = (const float*)d_in[7];
    const float* W_dt      = (const float*)d_in[8];
    const float* b_dt      = (const float*)d_in[9];
    const float* A_log     = (const float*)d_in[10];
    const float* D_skip    = (const float*)d_in[11];
    const float* W_out     = (const float*)d_in[12];
    const float* gamma     = (const float*)d_in[13];
    const float* beta      = (const float*)d_in[14];
    const float* W_phase   = (const float*)d_in[15];
    float* out = (float*)d_out;

    float* pxz;  cudaGetSymbolAddress((void**)&pxz,  g_xz);
    float* pxps; cudaGetSymbolAddress((void**)&pxps, g_xps);
    float* po;   cudaGetSymbolAddress((void**)&po,   g_o);
    uint32_t* pxperm;  cudaGetSymbolAddress((void**)&pxperm,  g_xperm);
    uint32_t* pwinp;   cudaGetSymbolAddress((void**)&pwinp,   g_winp);
    uint32_t* pxmperm; cudaGetSymbolAddress((void**)&pxmperm, g_xmperm);
    uint32_t* pwxp;    cudaGetSymbolAddress((void**)&pwxp,    g_wxp);
    uint32_t* pyperm;  cudaGetSymbolAddress((void**)&pyperm,  g_yperm);
    uint32_t* pwoutp;  cudaGetSymbolAddress((void**)&pwoutp,  g_woutp);

    /* 0) all operand permutes in one launch */
    perm_all_kernel<<<PERM_NA + PERM_NB1 + PERM_NB2 + PERM_NB3, 256>>>(
        x, W_in, W_out, W_x);

    /* 1) xz = x @ W_in : tensor bf16-split, 400 blocks, prefetched */
    gemm_bf16_kernel<16><<<dim3(16, 25, 1), 256>>>(
        pxperm, pwinp, pxz, 2 * DI, DM / 16, 0);

    /* 2) conv + SiLU -> g_xm + fragment-split g_xmperm */
    conv_silu_kernel<<<(MROWS * (DI / 4) + 255) / 256, 256>>>(conv_w, conv_b);

    /* 3) xp slices = x_m @ W_x : splitK=4 (300 blocks), prefetched */
    gemm_bf16_kernel<8><<<dim3(3, 25, XSPLIT), 256>>>(
        pxmperm, pwxp, pxps, XP_P, DI / 16, MROWS * XP_P);

    /* 4) xp slice-sum + phase add + dt + scan-stream pack */
    dt_phase_kernel<<<MROWS / 4, 256>>>(W_dt, b_dt, delta_mag,
                                        cos_phi, sin_phi, W_phase);

    /* 5) selective scan (d-pair warps, 4-step batched reduction) */
    scan_kernel<<<(B_SZ * NDP * 32) / 128, 128>>>(A_log, D_skip);

    /* 6) g_o slices = y @ W_out : splitK=4 (400 blocks), prefetched */
    gemm_bf16_kernel<8><<<dim3(4, 25, OSPLIT), 256>>>(
        pyperm, pwoutp, po, DM, DI / 16, MROWS * DM);

    /* 7) residual + slice-sum + LayerNorm -> out */
    ln_kernel<<<MROWS, DM>>>(x, gamma, beta, out);
}